// round 7
// baseline (speedup 1.0000x reference)
#include <cuda_runtime.h>
#include <mma.h>
#include <cstdint>
using namespace nvcuda;

// Problem constants (fixed by the reference)
#define BT      4096      // B * T_dec = B * T_enc = 2 * 2048
#define DM      1024      // d_model
#define NHEADS  16
#define DH      64
#define TDEC    2048
#define TENC    2048
#define NB      2

// Scratch (allocation-free): Q, K, V, Y buffers, each (4096 x 1024) fp32
__device__ float g_Q[BT * DM];
__device__ float g_K[BT * DM];
__device__ float g_V[BT * DM];
__device__ float g_Y[BT * DM];

// ---------------------------------------------------------------------------
// helpers
// ---------------------------------------------------------------------------
__device__ __forceinline__ void cp_async16(void* smem_dst, const void* gmem_src) {
    unsigned sa = (unsigned)__cvta_generic_to_shared(smem_dst);
    asm volatile("cp.async.cg.shared.global [%0], [%1], 16;\n" :: "r"(sa), "l"(gmem_src));
}
__device__ __forceinline__ void cp_commit() {
    asm volatile("cp.async.commit_group;\n");
}
__device__ __forceinline__ void cp_wait_all() {
    asm volatile("cp.async.wait_group 0;\n");
}
__device__ __forceinline__ float tf32_round(float v) {
    unsigned t;
    asm("cvt.rna.tf32.f32 %0, %1;" : "=r"(t) : "f"(v));
    return __uint_as_float(t);
}

// ---------------------------------------------------------------------------
// TF32 tiled GEMM, double-buffered cp.async, BK=32, fused bias epilogue.
// C = X @ W (X: MxK row-major, W: KxN row-major). Tile 128x128, 8 warps.
// grid = (N/128, rows/128); bm offset by moff tiles (for launch splitting).
// ---------------------------------------------------------------------------
#define GLDA 40     // 32 + 8 pad
#define GLDB 136    // 128 + 8 pad
#define GLDC 132    // 128 + 4 pad
// dynamic smem floats: stages 2*(128*40) + 2*(32*136) = 18944 ; Cs 128*132=16896 (aliased)
#define GEMM_SMEM_FLOATS (2 * 128 * GLDA + 2 * 32 * GLDB)
#define GEMM_SMEM_BYTES  (GEMM_SMEM_FLOATS * 4)

__global__ __launch_bounds__(256) void gemm_tf32_kernel(
    const float* __restrict__ X, const float* __restrict__ W,
    const float* __restrict__ bias, float* __restrict__ C,
    int K, int N, int moff, int do_round)
{
    extern __shared__ float sgm[];
    float (*As)[128 * GLDA] = reinterpret_cast<float (*)[128 * GLDA]>(sgm);
    float (*Bs)[32 * GLDB]  = reinterpret_cast<float (*)[32 * GLDB]>(sgm + 2 * 128 * GLDA);
    float* Cs = sgm;   // aliases stage memory in epilogue

    const int bm = (blockIdx.y + moff) * 128;
    const int bn = blockIdx.x * 128;
    const int tid = threadIdx.x;
    const int warp = tid >> 5;
    const int wm = warp >> 1;   // 0..3 -> row block of 32
    const int wn = warp & 1;    // 0..1 -> col block of 64

    wmma::fragment<wmma::accumulator, 16, 16, 8, float> acc[2][4];
    #pragma unroll
    for (int i = 0; i < 2; i++)
        #pragma unroll
        for (int j = 0; j < 4; j++)
            wmma::fill_fragment(acc[i][j], 0.0f);

    // stage loader: A tile 128x32 (1024 f4), B tile 32x128 (1024 f4); 4+4 per thread
    auto load_stage = [&](int s, int k0) {
        #pragma unroll
        for (int i = tid; i < 1024; i += 256) {
            int row = i >> 3, c4 = i & 7;
            cp_async16(&As[s][row * GLDA + c4 * 4],
                       &X[(size_t)(bm + row) * K + k0 + c4 * 4]);
        }
        #pragma unroll
        for (int i = tid; i < 1024; i += 256) {
            int row = i >> 5, c4 = i & 31;
            cp_async16(&Bs[s][row * GLDB + c4 * 4],
                       &W[(size_t)(k0 + row) * N + bn + c4 * 4]);
        }
        cp_commit();
    };

    const int nk = K / 32;
    load_stage(0, 0);

    for (int kt = 0; kt < nk; kt++) {
        cp_wait_all();
        __syncthreads();
        if (kt + 1 < nk) load_stage((kt + 1) & 1, (kt + 1) * 32);
        const int s = kt & 1;

        #pragma unroll
        for (int kk = 0; kk < 32; kk += 8) {
            wmma::fragment<wmma::matrix_a, 16, 16, 8, wmma::precision::tf32, wmma::row_major> afr[2];
            wmma::fragment<wmma::matrix_b, 16, 16, 8, wmma::precision::tf32, wmma::row_major> bfr[4];
            #pragma unroll
            for (int mt = 0; mt < 2; mt++) {
                wmma::load_matrix_sync(afr[mt], &As[s][(wm * 32 + mt * 16) * GLDA + kk], GLDA);
                #pragma unroll
                for (int e = 0; e < afr[mt].num_elements; e++)
                    afr[mt].x[e] = wmma::__float_to_tf32(afr[mt].x[e]);
            }
            #pragma unroll
            for (int nt = 0; nt < 4; nt++) {
                wmma::load_matrix_sync(bfr[nt], &Bs[s][kk * GLDB + wn * 64 + nt * 16], GLDB);
                #pragma unroll
                for (int e = 0; e < bfr[nt].num_elements; e++)
                    bfr[nt].x[e] = wmma::__float_to_tf32(bfr[nt].x[e]);
            }
            #pragma unroll
            for (int mt = 0; mt < 2; mt++)
                #pragma unroll
                for (int nt = 0; nt < 4; nt++)
                    wmma::mma_sync(acc[mt][nt], afr[mt], bfr[nt], acc[mt][nt]);
        }
    }

    // Epilogue: fragments -> smem, then bias(+round) -> global, coalesced
    __syncthreads();   // all warps done reading stage smem
    #pragma unroll
    for (int mt = 0; mt < 2; mt++)
        #pragma unroll
        for (int nt = 0; nt < 4; nt++)
            wmma::store_matrix_sync(
                &Cs[(size_t)(wm * 32 + mt * 16) * GLDC + wn * 64 + nt * 16],
                acc[mt][nt], GLDC, wmma::mem_row_major);
    __syncthreads();

    {
        const int row = tid >> 1;          // 2 threads per row
        const int half = tid & 1;          // 64 cols each
        const float* src = &Cs[(size_t)row * GLDC + half * 64];
        const float* bsrc = &bias[bn + half * 64];
        float* dst = &C[(size_t)(bm + row) * N + bn + half * 64];
        if (do_round) {
            #pragma unroll
            for (int j = 0; j < 64; j += 4) {
                float4 v;
                v.x = tf32_round(src[j + 0] + bsrc[j + 0]);
                v.y = tf32_round(src[j + 1] + bsrc[j + 1]);
                v.z = tf32_round(src[j + 2] + bsrc[j + 2]);
                v.w = tf32_round(src[j + 3] + bsrc[j + 3]);
                *reinterpret_cast<float4*>(&dst[j]) = v;
            }
        } else {
            #pragma unroll
            for (int j = 0; j < 64; j += 4) {
                float4 v;
                v.x = src[j + 0] + bsrc[j + 0];
                v.y = src[j + 1] + bsrc[j + 1];
                v.z = src[j + 2] + bsrc[j + 2];
                v.w = src[j + 3] + bsrc[j + 3];
                *reinterpret_cast<float4*>(&dst[j]) = v;
            }
        }
    }
}

// ---------------------------------------------------------------------------
// Flash attention, TF32 wmma, K-chunk = 128, cp.async double-buffered K/V.
// One block = one (b,h) x 64 query rows. grid = (TDEC/64, B*NHEADS), 512 thr.
// ---------------------------------------------------------------------------
#define KC      128
#define ALD     72    // 64 + 8
#define SLD     136   // 128 + 8
#define NJT     (TENC / KC)
#define ATT_SMEM_BYTES ((4608 + 4608 + 8704 + 18432 + 18432 + 128) * 4)

__global__ __launch_bounds__(512) void attn_kernel(
    const float* __restrict__ Q, const float* __restrict__ K,
    const float* __restrict__ V, float* __restrict__ Y)
{
    extern __shared__ float sm[];
    float* Qs  = sm;                    // 64 x ALD
    float* Os  = Qs + 64 * ALD;         // 64 x ALD
    float* Ss  = Os + 64 * ALD;         // 64 x SLD
    float* Ks0 = Ss + 64 * SLD;         // [2][KC x ALD]
    float* Vs0 = Ks0 + 2 * KC * ALD;    // [2][KC x ALD]
    float* m_s = Vs0 + 2 * KC * ALD;    // 64
    float* l_s = m_s + 64;              // 64

    const int bh = blockIdx.y;
    const int b  = bh >> 4;             // NHEADS = 16
    const int h  = bh & 15;
    const int q0 = blockIdx.x * 64;
    const int tid = threadIdx.x;
    const int warp = tid >> 5;
    const int wm = warp >> 2;           // 0..3 -> 16-row stripe
    const int wn = warp & 3;            // 0..3 -> col quarter
    const float scale = 0.125f;         // 1/sqrt(64); pow2 keeps tf32 exact

    auto prefetch_kv = [&](int s, int jt) {
        float* Ks = Ks0 + s * KC * ALD;
        float* Vs = Vs0 + s * KC * ALD;
        const int j0 = jt * KC;
        #pragma unroll
        for (int i = tid; i < 2048; i += 512) {
            int row = i >> 4, c4 = i & 15;
            size_t g = (size_t)(b * TENC + j0 + row) * DM + h * DH + c4 * 4;
            cp_async16(&Ks[row * ALD + c4 * 4], &K[g]);
            cp_async16(&Vs[row * ALD + c4 * 4], &V[g]);
        }
        cp_commit();
    };

    // Load Q tile (64x64), pre-scaled
    #pragma unroll
    for (int i = tid; i < 1024; i += 512) {
        int row = i >> 4, c4 = i & 15;
        float4 v = *reinterpret_cast<const float4*>(
            &Q[(size_t)(b * TDEC + q0 + row) * DM + h * DH + c4 * 4]);
        float* dst = &Qs[row * ALD + c4 * 4];
        dst[0] = v.x * scale; dst[1] = v.y * scale;
        dst[2] = v.z * scale; dst[3] = v.w * scale;
    }
    // Init O accumulator + stats (8 threads per row, 8 cols each)
    {
        int r = tid >> 3, seg = tid & 7;
        float* Or = &Os[r * ALD + seg * 8];
        #pragma unroll
        for (int c = 0; c < 8; c++) Or[c] = 0.0f;
        if (tid < 64) { m_s[tid] = -1e30f; l_s[tid] = 0.0f; }
    }
    prefetch_kv(0, 0);

    for (int jt = 0; jt < NJT; jt++) {
        cp_wait_all();
        __syncthreads();
        if (jt + 1 < NJT) prefetch_kv((jt + 1) & 1, jt + 1);
        const int st = jt & 1;
        float* Ks = Ks0 + st * KC * ALD;
        float* Vs = Vs0 + st * KC * ALD;

        // ---- S = Qs @ Ks^T : 64 x 128, warp tile 16 x 32 ----
        {
            wmma::fragment<wmma::accumulator, 16, 16, 8, float> sacc[2];
            wmma::fill_fragment(sacc[0], 0.0f);
            wmma::fill_fragment(sacc[1], 0.0f);
            #pragma unroll
            for (int kk = 0; kk < 64; kk += 8) {
                wmma::fragment<wmma::matrix_a, 16, 16, 8, wmma::precision::tf32, wmma::row_major> afr;
                wmma::load_matrix_sync(afr, &Qs[(wm * 16) * ALD + kk], ALD);
                #pragma unroll
                for (int nt = 0; nt < 2; nt++) {
                    wmma::fragment<wmma::matrix_b, 16, 16, 8, wmma::precision::tf32, wmma::col_major> bfr;
                    wmma::load_matrix_sync(bfr, &Ks[(wn * 32 + nt * 16) * ALD + kk], ALD);
                    wmma::mma_sync(sacc[nt], afr, bfr, sacc[nt]);
                }
            }
            #pragma unroll
            for (int nt = 0; nt < 2; nt++)
                wmma::store_matrix_sync(&Ss[(wm * 16) * SLD + wn * 32 + nt * 16],
                                        sacc[nt], SLD, wmma::mem_row_major);
        }
        __syncthreads();

        // ---- online softmax: 8 threads/row, 16 strided cols each ----
        {
            int r = tid >> 3, seg = tid & 7;
            float* Sr = &Ss[r * SLD];
            float mx = -1e30f;
            #pragma unroll
            for (int c = 0; c < 16; c++) mx = fmaxf(mx, Sr[seg + 8 * c]);
            mx = fmaxf(mx, __shfl_xor_sync(0xffffffffu, mx, 1));
            mx = fmaxf(mx, __shfl_xor_sync(0xffffffffu, mx, 2));
            mx = fmaxf(mx, __shfl_xor_sync(0xffffffffu, mx, 4));
            float mold = m_s[r];
            float mnew = fmaxf(mold, mx);
            float alpha = __expf(mold - mnew);
            float sum = 0.0f;
            #pragma unroll
            for (int c = 0; c < 16; c++) {
                float p = __expf(Sr[seg + 8 * c] - mnew);
                sum += p;
                Sr[seg + 8 * c] = tf32_round(p);
            }
            sum += __shfl_xor_sync(0xffffffffu, sum, 1);
            sum += __shfl_xor_sync(0xffffffffu, sum, 2);
            sum += __shfl_xor_sync(0xffffffffu, sum, 4);
            float* Or = &Os[r * ALD + seg * 8];
            #pragma unroll
            for (int c = 0; c < 8; c++) Or[c] *= alpha;
            if (seg == 0) {
                m_s[r] = mnew;
                l_s[r] = l_s[r] * alpha + sum;
            }
        }
        __syncthreads();

        // ---- O += P @ V : 64x64 += (64x128)@(128x64), warp tile 16x16 ----
        {
            wmma::fragment<wmma::accumulator, 16, 16, 8, float> oacc;
            wmma::load_matrix_sync(oacc, &Os[(wm * 16) * ALD + wn * 16],
                                   ALD, wmma::mem_row_major);
            #pragma unroll
            for (int kk = 0; kk < KC; kk += 8) {
                wmma::fragment<wmma::matrix_a, 16, 16, 8, wmma::precision::tf32, wmma::row_major> afr;
                wmma::load_matrix_sync(afr, &Ss[(wm * 16) * SLD + kk], SLD);
                wmma::fragment<wmma::matrix_b, 16, 16, 8, wmma::precision::tf32, wmma::row_major> bfr;
                wmma::load_matrix_sync(bfr, &Vs[kk * ALD + wn * 16], ALD);
                wmma::mma_sync(oacc, afr, bfr, oacc);
            }
            wmma::store_matrix_sync(&Os[(wm * 16) * ALD + wn * 16],
                                    oacc, ALD, wmma::mem_row_major);
        }
    }
    __syncthreads();

    // Epilogue: Y[b, q0+r, h*64 + d] = Os[r][d] / l[r]
    {
        int r = tid >> 3, seg = tid & 7;
        float inv_l = 1.0f / l_s[r];
        const float* Or = &Os[r * ALD + seg * 8];
        float* dst = &Y[(size_t)(b * TDEC + q0 + r) * DM + h * DH + seg * 8];
        #pragma unroll
        for (int c4 = 0; c4 < 2; c4++) {
            float4 v;
            v.x = Or[c4 * 4 + 0] * inv_l;
            v.y = Or[c4 * 4 + 1] * inv_l;
            v.z = Or[c4 * 4 + 2] * inv_l;
            v.w = Or[c4 * 4 + 3] * inv_l;
            *reinterpret_cast<float4*>(&dst[c4 * 4]) = v;
        }
    }
}

// ---------------------------------------------------------------------------
// Launcher
// Launch order puts attn_kernel at index 5 so ncu (-s 5 -c 1) profiles it.
// ---------------------------------------------------------------------------
extern "C" void kernel_launch(void* const* d_in, const int* in_sizes, int n_in,
                              void* d_out, int out_size)
{
    const float* tgt    = (const float*)d_in[0];
    const float* memory = (const float*)d_in[1];
    const float* W_q    = (const float*)d_in[2];
    const float* b_q    = (const float*)d_in[3];
    const float* W_k    = (const float*)d_in[4];
    const float* b_k    = (const float*)d_in[5];
    const float* W_v    = (const float*)d_in[6];
    const float* b_v    = (const float*)d_in[7];
    const float* W_o    = (const float*)d_in[8];
    const float* b_o    = (const float*)d_in[9];
    float* out = (float*)d_out;

    float *gQ, *gK, *gV, *gY;
    cudaGetSymbolAddress((void**)&gQ, g_Q);
    cudaGetSymbolAddress((void**)&gK, g_K);
    cudaGetSymbolAddress((void**)&gV, g_V);
    cudaGetSymbolAddress((void**)&gY, g_Y);

    cudaFuncSetAttribute(gemm_tf32_kernel, cudaFuncAttributeMaxDynamicSharedMemorySize,
                         GEMM_SMEM_BYTES);
    cudaFuncSetAttribute(attn_kernel, cudaFuncAttributeMaxDynamicSharedMemorySize,
                         ATT_SMEM_BYTES);

    dim3 ghalf(DM / 128, BT / 256);   // (8, 16) -- half of the M rows
    dim3 gfull(DM / 128, BT / 128);   // (8, 32)

    // 0,1: Q projection (split in two for profiling alignment)
    gemm_tf32_kernel<<<ghalf, 256, GEMM_SMEM_BYTES>>>(tgt, W_q, b_q, gQ, DM, DM, 0, 1);
    gemm_tf32_kernel<<<ghalf, 256, GEMM_SMEM_BYTES>>>(tgt, W_q, b_q, gQ, DM, DM, 16, 1);
    // 2,3: K projection (split)
    gemm_tf32_kernel<<<ghalf, 256, GEMM_SMEM_BYTES>>>(memory, W_k, b_k, gK, DM, DM, 0, 1);
    gemm_tf32_kernel<<<ghalf, 256, GEMM_SMEM_BYTES>>>(memory, W_k, b_k, gK, DM, DM, 16, 1);
    // 4: V projection
    gemm_tf32_kernel<<<gfull, 256, GEMM_SMEM_BYTES>>>(memory, W_v, b_v, gV, DM, DM, 0, 1);
    // 5: attention  (profiled launch)
    attn_kernel<<<dim3(TDEC / 64, NB * NHEADS), 512, ATT_SMEM_BYTES>>>(gQ, gK, gV, gY);
    // 6: output projection
    gemm_tf32_kernel<<<gfull, 256, GEMM_SMEM_BYTES>>>(gY, W_o, b_o, out, DM, DM, 0, 0);
}

// round 10
// speedup vs baseline: 1.0847x; 1.0847x over previous
#include <cuda_runtime.h>
#include <mma.h>
#include <cstdint>
using namespace nvcuda;

// Problem constants (fixed by the reference)
#define BT      4096      // B * T_dec = B * T_enc = 2 * 2048
#define DM      1024      // d_model
#define NHEADS  16
#define DH      64
#define TDEC    2048
#define TENC    2048
#define NB      2

// Scratch (allocation-free)
__device__ float g_Q[BT * DM];
__device__ float g_K[BT * DM];
__device__ float g_V[BT * DM];
__device__ float g_Y[BT * DM];
__device__ float g_Xr[BT * DM];    // tgt, tf32-rounded
__device__ float g_Mr[BT * DM];    // memory, tf32-rounded
__device__ float g_Wq[DM * DM];
__device__ float g_Wk[DM * DM];
__device__ float g_Wv[DM * DM];
__device__ float g_Wo[DM * DM];

// ---------------------------------------------------------------------------
// helpers
// ---------------------------------------------------------------------------
__device__ __forceinline__ void cp_async16(void* smem_dst, const void* gmem_src) {
    unsigned sa = (unsigned)__cvta_generic_to_shared(smem_dst);
    asm volatile("cp.async.cg.shared.global [%0], [%1], 16;\n" :: "r"(sa), "l"(gmem_src));
}
__device__ __forceinline__ void cp_commit() {
    asm volatile("cp.async.commit_group;\n");
}
__device__ __forceinline__ void cp_wait_all() {
    asm volatile("cp.async.wait_group 0;\n");
}
__device__ __forceinline__ float tf32_round(float v) {
    unsigned t;
    asm("cvt.rna.tf32.f32 %0, %1;" : "=r"(t) : "f"(v));
    return __uint_as_float(t);
}

// ---------------------------------------------------------------------------
// Fused tf32 pre-round of three tensors (grid-stride, float4)
// ---------------------------------------------------------------------------
__global__ void round3_kernel(const float* __restrict__ s1, float* __restrict__ d1, int n1,
                              const float* __restrict__ s2, float* __restrict__ d2, int n2,
                              const float* __restrict__ s3, float* __restrict__ d3, int n3)
{
    const int total4 = (n1 + n2 + n3) >> 2;
    for (int i = blockIdx.x * blockDim.x + threadIdx.x; i < total4;
         i += gridDim.x * blockDim.x) {
        int idx = i << 2;
        const float* s; float* d;
        if (idx < n1)            { s = s1 + idx; d = d1 + idx; }
        else if (idx < n1 + n2)  { s = s2 + (idx - n1); d = d2 + (idx - n1); }
        else                     { s = s3 + (idx - n1 - n2); d = d3 + (idx - n1 - n2); }
        float4 v = *reinterpret_cast<const float4*>(s);
        v.x = tf32_round(v.x); v.y = tf32_round(v.y);
        v.z = tf32_round(v.z); v.w = tf32_round(v.w);
        *reinterpret_cast<float4*>(d) = v;
    }
}

// ---------------------------------------------------------------------------
// TF32 tiled GEMM, double-buffered cp.async, BK=32, fused bias epilogue.
// Inputs MUST be pre-rounded to tf32 (no F2FP in the mainloop).
// C = X @ W (X: MxK row-major, W: KxN row-major). Tile 128x128, 8 warps.
// ---------------------------------------------------------------------------
#define GLDA 40     // 32 + 8 pad
#define GLDB 136    // 128 + 8 pad
#define GLDC 132    // 128 + 4 pad
#define GEMM_SMEM_FLOATS (2 * 128 * GLDA + 2 * 32 * GLDB)
#define GEMM_SMEM_BYTES  (GEMM_SMEM_FLOATS * 4)

__global__ __launch_bounds__(256, 2) void gemm_tf32_kernel(
    const float* __restrict__ X, const float* __restrict__ W,
    const float* __restrict__ bias, float* __restrict__ C,
    int K, int N, int do_round)
{
    extern __shared__ float sgm[];
    float (*As)[128 * GLDA] = reinterpret_cast<float (*)[128 * GLDA]>(sgm);
    float (*Bs)[32 * GLDB]  = reinterpret_cast<float (*)[32 * GLDB]>(sgm + 2 * 128 * GLDA);
    float* Cs = sgm;   // aliases stage memory in epilogue

    const int bm = blockIdx.y * 128;
    const int bn = blockIdx.x * 128;
    const int tid = threadIdx.x;
    const int warp = tid >> 5;
    const int wm = warp >> 1;   // 0..3 -> row block of 32
    const int wn = warp & 1;    // 0..1 -> col block of 64

    wmma::fragment<wmma::accumulator, 16, 16, 8, float> acc[2][4];
    #pragma unroll
    for (int i = 0; i < 2; i++)
        #pragma unroll
        for (int j = 0; j < 4; j++)
            wmma::fill_fragment(acc[i][j], 0.0f);

    auto load_stage = [&](int s, int k0) {
        #pragma unroll
        for (int i = tid; i < 1024; i += 256) {
            int row = i >> 3, c4 = i & 7;
            cp_async16(&As[s][row * GLDA + c4 * 4],
                       &X[(size_t)(bm + row) * K + k0 + c4 * 4]);
        }
        #pragma unroll
        for (int i = tid; i < 1024; i += 256) {
            int row = i >> 5, c4 = i & 31;
            cp_async16(&Bs[s][row * GLDB + c4 * 4],
                       &W[(size_t)(k0 + row) * N + bn + c4 * 4]);
        }
        cp_commit();
    };

    const int nk = K / 32;
    load_stage(0, 0);

    for (int kt = 0; kt < nk; kt++) {
        cp_wait_all();
        __syncthreads();
        if (kt + 1 < nk) load_stage((kt + 1) & 1, (kt + 1) * 32);
        const int s = kt & 1;

        #pragma unroll
        for (int kk = 0; kk < 32; kk += 8) {
            wmma::fragment<wmma::matrix_a, 16, 16, 8, wmma::precision::tf32, wmma::row_major> afr[2];
            wmma::fragment<wmma::matrix_b, 16, 16, 8, wmma::precision::tf32, wmma::row_major> bfr[4];
            #pragma unroll
            for (int mt = 0; mt < 2; mt++)
                wmma::load_matrix_sync(afr[mt], &As[s][(wm * 32 + mt * 16) * GLDA + kk], GLDA);
            #pragma unroll
            for (int nt = 0; nt < 4; nt++)
                wmma::load_matrix_sync(bfr[nt], &Bs[s][kk * GLDB + wn * 64 + nt * 16], GLDB);
            #pragma unroll
            for (int mt = 0; mt < 2; mt++)
                #pragma unroll
                for (int nt = 0; nt < 4; nt++)
                    wmma::mma_sync(acc[mt][nt], afr[mt], bfr[nt], acc[mt][nt]);
        }
    }

    // Epilogue: fragments -> smem, then bias(+round) -> global, coalesced
    __syncthreads();
    #pragma unroll
    for (int mt = 0; mt < 2; mt++)
        #pragma unroll
        for (int nt = 0; nt < 4; nt++)
            wmma::store_matrix_sync(
                &Cs[(size_t)(wm * 32 + mt * 16) * GLDC + wn * 64 + nt * 16],
                acc[mt][nt], GLDC, wmma::mem_row_major);
    __syncthreads();

    {
        const int row = tid >> 1;          // 2 threads per row
        const int half = tid & 1;          // 64 cols each
        const float* src = &Cs[(size_t)row * GLDC + half * 64];
        const float* bsrc = &bias[bn + half * 64];
        float* dst = &C[(size_t)(bm + row) * N + bn + half * 64];
        if (do_round) {
            #pragma unroll
            for (int j = 0; j < 64; j += 4) {
                float4 v;
                v.x = tf32_round(src[j + 0] + bsrc[j + 0]);
                v.y = tf32_round(src[j + 1] + bsrc[j + 1]);
                v.z = tf32_round(src[j + 2] + bsrc[j + 2]);
                v.w = tf32_round(src[j + 3] + bsrc[j + 3]);
                *reinterpret_cast<float4*>(&dst[j]) = v;
            }
        } else {
            #pragma unroll
            for (int j = 0; j < 64; j += 4) {
                float4 v;
                v.x = src[j + 0] + bsrc[j + 0];
                v.y = src[j + 1] + bsrc[j + 1];
                v.z = src[j + 2] + bsrc[j + 2];
                v.w = src[j + 3] + bsrc[j + 3];
                *reinterpret_cast<float4*>(&dst[j]) = v;
            }
        }
    }
}

// ---------------------------------------------------------------------------
// Flash attention, TF32 wmma, K-chunk = 128, cp.async double-buffered K/V.
// One block = one (b,h) x 64 query rows. grid = (TDEC/64, B*NHEADS), 256 thr.
// Epilogue writes tf32-rounded Y so the O-projection GEMM needs no F2FP.
// ---------------------------------------------------------------------------
#define KC      128
#define ALD     72    // 64 + 8
#define SLD     136   // 128 + 8
#define NJT     (TENC / KC)
#define ATT_SMEM_BYTES ((4608 + 4608 + 8704 + 18432 + 18432 + 128) * 4)

__global__ __launch_bounds__(256) void attn_kernel(
    const float* __restrict__ Q, const float* __restrict__ K,
    const float* __restrict__ V, float* __restrict__ Y)
{
    extern __shared__ float sm[];
    float* Qs  = sm;                    // 64 x ALD
    float* Os  = Qs + 64 * ALD;         // 64 x ALD
    float* Ss  = Os + 64 * ALD;         // 64 x SLD
    float* Ks0 = Ss + 64 * SLD;         // [2][KC x ALD]
    float* Vs0 = Ks0 + 2 * KC * ALD;    // [2][KC x ALD]
    float* m_s = Vs0 + 2 * KC * ALD;    // 64
    float* l_s = m_s + 64;              // 64

    const int bh = blockIdx.y;
    const int b  = bh >> 4;
    const int h  = bh & 15;
    const int q0 = blockIdx.x * 64;
    const int tid = threadIdx.x;
    const int warp = tid >> 5;
    const int wm = warp >> 1;
    const int wn = warp & 1;
    const float scale = 0.125f;

    auto prefetch_kv = [&](int s, int jt) {
        float* Ks = Ks0 + s * KC * ALD;
        float* Vs = Vs0 + s * KC * ALD;
        const int j0 = jt * KC;
        #pragma unroll
        for (int i = tid; i < 2048; i += 256) {
            int row = i >> 4, c4 = i & 15;
            size_t g = (size_t)(b * TENC + j0 + row) * DM + h * DH + c4 * 4;
            cp_async16(&Ks[row * ALD + c4 * 4], &K[g]);
            cp_async16(&Vs[row * ALD + c4 * 4], &V[g]);
        }
        cp_commit();
    };

    #pragma unroll
    for (int i = tid; i < 1024; i += 256) {
        int row = i >> 4, c4 = i & 15;
        float4 v = *reinterpret_cast<const float4*>(
            &Q[(size_t)(b * TDEC + q0 + row) * DM + h * DH + c4 * 4]);
        float* dst = &Qs[row * ALD + c4 * 4];
        dst[0] = v.x * scale; dst[1] = v.y * scale;
        dst[2] = v.z * scale; dst[3] = v.w * scale;
    }
    {
        int r = tid >> 2, seg = tid & 3;
        float* Or = &Os[r * ALD + seg * 16];
        #pragma unroll
        for (int c = 0; c < 16; c++) Or[c] = 0.0f;
        if (tid < 64) { m_s[tid] = -1e30f; l_s[tid] = 0.0f; }
    }
    prefetch_kv(0, 0);

    for (int jt = 0; jt < NJT; jt++) {
        cp_wait_all();
        __syncthreads();
        if (jt + 1 < NJT) prefetch_kv((jt + 1) & 1, jt + 1);
        const int st = jt & 1;
        float* Ks = Ks0 + st * KC * ALD;
        float* Vs = Vs0 + st * KC * ALD;

        // S = Qs @ Ks^T : 64 x 128, warp tile 16 x 64
        {
            wmma::fragment<wmma::accumulator, 16, 16, 8, float> sacc[4];
            #pragma unroll
            for (int nt = 0; nt < 4; nt++) wmma::fill_fragment(sacc[nt], 0.0f);
            #pragma unroll
            for (int kk = 0; kk < 64; kk += 8) {
                wmma::fragment<wmma::matrix_a, 16, 16, 8, wmma::precision::tf32, wmma::row_major> afr;
                wmma::load_matrix_sync(afr, &Qs[(wm * 16) * ALD + kk], ALD);
                #pragma unroll
                for (int nt = 0; nt < 4; nt++) {
                    wmma::fragment<wmma::matrix_b, 16, 16, 8, wmma::precision::tf32, wmma::col_major> bfr;
                    wmma::load_matrix_sync(bfr, &Ks[(wn * 64 + nt * 16) * ALD + kk], ALD);
                    wmma::mma_sync(sacc[nt], afr, bfr, sacc[nt]);
                }
            }
            #pragma unroll
            for (int nt = 0; nt < 4; nt++)
                wmma::store_matrix_sync(&Ss[(wm * 16) * SLD + wn * 64 + nt * 16],
                                        sacc[nt], SLD, wmma::mem_row_major);
        }
        __syncthreads();

        // online softmax: 4 threads/row, 32 strided cols each
        {
            int r = tid >> 2, seg = tid & 3;
            float* Sr = &Ss[r * SLD];
            float mx = -1e30f;
            #pragma unroll
            for (int c = 0; c < 32; c++) mx = fmaxf(mx, Sr[seg + 4 * c]);
            mx = fmaxf(mx, __shfl_xor_sync(0xffffffffu, mx, 1));
            mx = fmaxf(mx, __shfl_xor_sync(0xffffffffu, mx, 2));
            float mold = m_s[r];
            float mnew = fmaxf(mold, mx);
            float alpha = __expf(mold - mnew);
            float sum = 0.0f;
            #pragma unroll
            for (int c = 0; c < 32; c++) {
                float p = __expf(Sr[seg + 4 * c] - mnew);
                sum += p;
                Sr[seg + 4 * c] = tf32_round(p);
            }
            sum += __shfl_xor_sync(0xffffffffu, sum, 1);
            sum += __shfl_xor_sync(0xffffffffu, sum, 2);
            float* Or = &Os[r * ALD + seg * 16];
            #pragma unroll
            for (int c = 0; c < 16; c++) Or[c] *= alpha;
            if (seg == 0) {
                m_s[r] = mnew;
                l_s[r] = l_s[r] * alpha + sum;
            }
        }
        __syncthreads();

        // O += P @ V : 64 x 64 += (64x128)@(128x64), warp tile 16x32
        {
            wmma::fragment<wmma::accumulator, 16, 16, 8, float> oacc[2];
            #pragma unroll
            for (int nt = 0; nt < 2; nt++)
                wmma::load_matrix_sync(oacc[nt], &Os[(wm * 16) * ALD + wn * 32 + nt * 16],
                                       ALD, wmma::mem_row_major);
            #pragma unroll
            for (int kk = 0; kk < KC; kk += 8) {
                wmma::fragment<wmma::matrix_a, 16, 16, 8, wmma::precision::tf32, wmma::row_major> afr;
                wmma::load_matrix_sync(afr, &Ss[(wm * 16) * SLD + kk], SLD);
                #pragma unroll
                for (int nt = 0; nt < 2; nt++) {
                    wmma::fragment<wmma::matrix_b, 16, 16, 8, wmma::precision::tf32, wmma::row_major> bfr;
                    wmma::load_matrix_sync(bfr, &Vs[kk * ALD + wn * 32 + nt * 16], ALD);
                    wmma::mma_sync(oacc[nt], afr, bfr, oacc[nt]);
                }
            }
            #pragma unroll
            for (int nt = 0; nt < 2; nt++)
                wmma::store_matrix_sync(&Os[(wm * 16) * ALD + wn * 32 + nt * 16],
                                        oacc[nt], ALD, wmma::mem_row_major);
        }
    }
    __syncthreads();

    // Epilogue: Y = tf32_round(Os / l) so the O-projection needs no F2FP
    {
        int r = tid >> 2, seg = tid & 3;
        float inv_l = 1.0f / l_s[r];
        const float* Or = &Os[r * ALD + seg * 16];
        float* dst = &Y[(size_t)(b * TDEC + q0 + r) * DM + h * DH + seg * 16];
        #pragma unroll
        for (int c4 = 0; c4 < 4; c4++) {
            float4 v;
            v.x = tf32_round(Or[c4 * 4 + 0] * inv_l);
            v.y = tf32_round(Or[c4 * 4 + 1] * inv_l);
            v.z = tf32_round(Or[c4 * 4 + 2] * inv_l);
            v.w = tf32_round(Or[c4 * 4 + 3] * inv_l);
            *reinterpret_cast<float4*>(&dst[c4 * 4]) = v;
        }
    }
}

// ---------------------------------------------------------------------------
// Launcher.  Launch index 5 = attn_kernel (ncu -s 5 -c 1 profiles it).
// ---------------------------------------------------------------------------
extern "C" void kernel_launch(void* const* d_in, const int* in_sizes, int n_in,
                              void* d_out, int out_size)
{
    const float* tgt    = (const float*)d_in[0];
    const float* memory = (const float*)d_in[1];
    const float* W_q    = (const float*)d_in[2];
    const float* b_q    = (const float*)d_in[3];
    const float* W_k    = (const float*)d_in[4];
    const float* b_k    = (const float*)d_in[5];
    const float* W_v    = (const float*)d_in[6];
    const float* b_v    = (const float*)d_in[7];
    const float* W_o    = (const float*)d_in[8];
    const float* b_o    = (const float*)d_in[9];
    float* out = (float*)d_out;

    float *gQ, *gK, *gV, *gY, *gXr, *gMr, *wq, *wk, *wv, *wo;
    cudaGetSymbolAddress((void**)&gQ, g_Q);
    cudaGetSymbolAddress((void**)&gK, g_K);
    cudaGetSymbolAddress((void**)&gV, g_V);
    cudaGetSymbolAddress((void**)&gY, g_Y);
    cudaGetSymbolAddress((void**)&gXr, g_Xr);
    cudaGetSymbolAddress((void**)&gMr, g_Mr);
    cudaGetSymbolAddress((void**)&wq, g_Wq);
    cudaGetSymbolAddress((void**)&wk, g_Wk);
    cudaGetSymbolAddress((void**)&wv, g_Wv);
    cudaGetSymbolAddress((void**)&wo, g_Wo);

    cudaFuncSetAttribute(gemm_tf32_kernel, cudaFuncAttributeMaxDynamicSharedMemorySize,
                         GEMM_SMEM_BYTES);
    cudaFuncSetAttribute(attn_kernel, cudaFuncAttributeMaxDynamicSharedMemorySize,
                         ATT_SMEM_BYTES);

    const int nact = BT * DM;    // 4M
    const int nw = DM * DM;      // 1M

    // 0,1: pre-round all GEMM operands to tf32
    round3_kernel<<<1184, 256>>>(tgt, gXr, nact, W_q, wq, nw, W_k, wk, nw);
    round3_kernel<<<1184, 256>>>(memory, gMr, nact, W_v, wv, nw, W_o, wo, nw);

    dim3 ggrid(DM / 128, BT / 128);   // (8, 32)
    // 2,3,4: projections with fused bias + tf32 round
    gemm_tf32_kernel<<<ggrid, 256, GEMM_SMEM_BYTES>>>(gXr, wq, b_q, gQ, DM, DM, 1);
    gemm_tf32_kernel<<<ggrid, 256, GEMM_SMEM_BYTES>>>(gMr, wk, b_k, gK, DM, DM, 1);
    gemm_tf32_kernel<<<ggrid, 256, GEMM_SMEM_BYTES>>>(gMr, wv, b_v, gV, DM, DM, 1);
    // 5: attention (profiled launch)
    attn_kernel<<<dim3(TDEC / 64, NB * NHEADS), 256, ATT_SMEM_BYTES>>>(gQ, gK, gV, gY);
    // 6: output projection (no rounding on final output)
    gemm_tf32_kernel<<<ggrid, 256, GEMM_SMEM_BYTES>>>(gY, wo, b_o, out, DM, DM, 0);
}

// round 11
// speedup vs baseline: 1.3106x; 1.2082x over previous
#include <cuda_runtime.h>
#include <mma.h>
#include <cstdint>
using namespace nvcuda;

// Problem constants (fixed by the reference)
#define BT      4096      // B * T_dec = B * T_enc = 2 * 2048
#define DM      1024      // d_model
#define NHEADS  16
#define DH      64
#define TDEC    2048
#define TENC    2048
#define NB      2

// Scratch (allocation-free)
__device__ float g_Q[BT * DM];
__device__ float g_K[BT * DM];
__device__ float g_V[BT * DM];
__device__ float g_Y[BT * DM];
__device__ float g_Xr[BT * DM];    // tgt, tf32-rounded
__device__ float g_Mr[BT * DM];    // memory, tf32-rounded
__device__ float g_Wq[DM * DM];
__device__ float g_Wk[DM * DM];
__device__ float g_Wv[DM * DM];
__device__ float g_Wo[DM * DM];

// ---------------------------------------------------------------------------
// helpers
// ---------------------------------------------------------------------------
__device__ __forceinline__ void cp_async16(void* smem_dst, const void* gmem_src) {
    unsigned sa = (unsigned)__cvta_generic_to_shared(smem_dst);
    asm volatile("cp.async.cg.shared.global [%0], [%1], 16;\n" :: "r"(sa), "l"(gmem_src));
}
__device__ __forceinline__ void cp_commit() {
    asm volatile("cp.async.commit_group;\n");
}
__device__ __forceinline__ void cp_wait_all() {
    asm volatile("cp.async.wait_group 0;\n");
}
__device__ __forceinline__ float tf32_round(float v) {
    unsigned t;
    asm("cvt.rna.tf32.f32 %0, %1;" : "=r"(t) : "f"(v));
    return __uint_as_float(t);
}
// PTX mma m16n8k8 tf32: D(16x8,f32) += A(16x8) * B(8x8); known fragment layouts.
__device__ __forceinline__ void mma16n8k8(float* c, const uint32_t* a, const uint32_t* b) {
    asm volatile(
        "mma.sync.aligned.m16n8k8.row.col.f32.tf32.tf32.f32 "
        "{%0,%1,%2,%3}, {%4,%5,%6,%7}, {%8,%9}, {%0,%1,%2,%3};\n"
        : "+f"(c[0]), "+f"(c[1]), "+f"(c[2]), "+f"(c[3])
        : "r"(a[0]), "r"(a[1]), "r"(a[2]), "r"(a[3]), "r"(b[0]), "r"(b[1]));
}

// ---------------------------------------------------------------------------
// Fused tf32 pre-round of three tensors (grid-stride, float4)
// ---------------------------------------------------------------------------
__global__ void round3_kernel(const float* __restrict__ s1, float* __restrict__ d1, int n1,
                              const float* __restrict__ s2, float* __restrict__ d2, int n2,
                              const float* __restrict__ s3, float* __restrict__ d3, int n3)
{
    const int total4 = (n1 + n2 + n3) >> 2;
    for (int i = blockIdx.x * blockDim.x + threadIdx.x; i < total4;
         i += gridDim.x * blockDim.x) {
        int idx = i << 2;
        const float* s; float* d;
        if (idx < n1)            { s = s1 + idx; d = d1 + idx; }
        else if (idx < n1 + n2)  { s = s2 + (idx - n1); d = d2 + (idx - n1); }
        else                     { s = s3 + (idx - n1 - n2); d = d3 + (idx - n1 - n2); }
        float4 v = *reinterpret_cast<const float4*>(s);
        v.x = tf32_round(v.x); v.y = tf32_round(v.y);
        v.z = tf32_round(v.z); v.w = tf32_round(v.w);
        *reinterpret_cast<float4*>(d) = v;
    }
}

// ---------------------------------------------------------------------------
// TF32 tiled GEMM, double-buffered cp.async, BK=32, fused bias epilogue.
// (unchanged from R10 passing version)
// ---------------------------------------------------------------------------
#define GLDA 40     // 32 + 8 pad
#define GLDB 136    // 128 + 8 pad
#define GLDC 132    // 128 + 4 pad
#define GEMM_SMEM_FLOATS (2 * 128 * GLDA + 2 * 32 * GLDB)
#define GEMM_SMEM_BYTES  (GEMM_SMEM_FLOATS * 4)

__global__ __launch_bounds__(256, 2) void gemm_tf32_kernel(
    const float* __restrict__ X, const float* __restrict__ W,
    const float* __restrict__ bias, float* __restrict__ C,
    int K, int N, int do_round)
{
    extern __shared__ float sgm[];
    float (*As)[128 * GLDA] = reinterpret_cast<float (*)[128 * GLDA]>(sgm);
    float (*Bs)[32 * GLDB]  = reinterpret_cast<float (*)[32 * GLDB]>(sgm + 2 * 128 * GLDA);
    float* Cs = sgm;

    const int bm = blockIdx.y * 128;
    const int bn = blockIdx.x * 128;
    const int tid = threadIdx.x;
    const int warp = tid >> 5;
    const int wm = warp >> 1;
    const int wn = warp & 1;

    wmma::fragment<wmma::accumulator, 16, 16, 8, float> acc[2][4];
    #pragma unroll
    for (int i = 0; i < 2; i++)
        #pragma unroll
        for (int j = 0; j < 4; j++)
            wmma::fill_fragment(acc[i][j], 0.0f);

    auto load_stage = [&](int s, int k0) {
        #pragma unroll
        for (int i = tid; i < 1024; i += 256) {
            int row = i >> 3, c4 = i & 7;
            cp_async16(&As[s][row * GLDA + c4 * 4],
                       &X[(size_t)(bm + row) * K + k0 + c4 * 4]);
        }
        #pragma unroll
        for (int i = tid; i < 1024; i += 256) {
            int row = i >> 5, c4 = i & 31;
            cp_async16(&Bs[s][row * GLDB + c4 * 4],
                       &W[(size_t)(k0 + row) * N + bn + c4 * 4]);
        }
        cp_commit();
    };

    const int nk = K / 32;
    load_stage(0, 0);

    for (int kt = 0; kt < nk; kt++) {
        cp_wait_all();
        __syncthreads();
        if (kt + 1 < nk) load_stage((kt + 1) & 1, (kt + 1) * 32);
        const int s = kt & 1;

        #pragma unroll
        for (int kk = 0; kk < 32; kk += 8) {
            wmma::fragment<wmma::matrix_a, 16, 16, 8, wmma::precision::tf32, wmma::row_major> afr[2];
            wmma::fragment<wmma::matrix_b, 16, 16, 8, wmma::precision::tf32, wmma::row_major> bfr[4];
            #pragma unroll
            for (int mt = 0; mt < 2; mt++)
                wmma::load_matrix_sync(afr[mt], &As[s][(wm * 32 + mt * 16) * GLDA + kk], GLDA);
            #pragma unroll
            for (int nt = 0; nt < 4; nt++)
                wmma::load_matrix_sync(bfr[nt], &Bs[s][kk * GLDB + wn * 64 + nt * 16], GLDB);
            #pragma unroll
            for (int mt = 0; mt < 2; mt++)
                #pragma unroll
                for (int nt = 0; nt < 4; nt++)
                    wmma::mma_sync(acc[mt][nt], afr[mt], bfr[nt], acc[mt][nt]);
        }
    }

    __syncthreads();
    #pragma unroll
    for (int mt = 0; mt < 2; mt++)
        #pragma unroll
        for (int nt = 0; nt < 4; nt++)
            wmma::store_matrix_sync(
                &Cs[(size_t)(wm * 32 + mt * 16) * GLDC + wn * 64 + nt * 16],
                acc[mt][nt], GLDC, wmma::mem_row_major);
    __syncthreads();

    {
        const int row = tid >> 1;
        const int half = tid & 1;
        const float* src = &Cs[(size_t)row * GLDC + half * 64];
        const float* bsrc = &bias[bn + half * 64];
        float* dst = &C[(size_t)(bm + row) * N + bn + half * 64];
        if (do_round) {
            #pragma unroll
            for (int j = 0; j < 64; j += 4) {
                float4 v;
                v.x = tf32_round(src[j + 0] + bsrc[j + 0]);
                v.y = tf32_round(src[j + 1] + bsrc[j + 1]);
                v.z = tf32_round(src[j + 2] + bsrc[j + 2]);
                v.w = tf32_round(src[j + 3] + bsrc[j + 3]);
                *reinterpret_cast<float4*>(&dst[j]) = v;
            }
        } else {
            #pragma unroll
            for (int j = 0; j < 64; j += 4) {
                float4 v;
                v.x = src[j + 0] + bsrc[j + 0];
                v.y = src[j + 1] + bsrc[j + 1];
                v.z = src[j + 2] + bsrc[j + 2];
                v.w = src[j + 3] + bsrc[j + 3];
                *reinterpret_cast<float4*>(&dst[j]) = v;
            }
        }
    }
}

// ---------------------------------------------------------------------------
// Flash attention v2: KC=64, 2 CTAs/SM, register-resident O via PTX mma.
// One block = one (b,h) x 64 query rows. grid = (TDEC/64, B*NHEADS), 256 thr.
//  - S = Q K^T via wmma into smem Ss (64x64)
//  - softmax on Ss (publishes per-row alpha, m, l)
//  - O += P V via mma.m16n8k8 with O in registers (known acc layout)
// smem: Qs 64x72 | Ss 64x72 | K/V 2 stages x 64x72 each | m,l,alpha 3x64
// = 27840 floats = 111360 B -> 2 CTAs/SM.
// ---------------------------------------------------------------------------
#define KC      64
#define ALD     72    // 64 + 8
#define NJT     (TENC / KC)      // 32
#define ATT_SMEM_FLOATS (4608 + 4608 + 4 * 4608 + 192)
#define ATT_SMEM_BYTES  (ATT_SMEM_FLOATS * 4)

__global__ __launch_bounds__(256, 2) void attn_kernel(
    const float* __restrict__ Q, const float* __restrict__ K,
    const float* __restrict__ V, float* __restrict__ Y)
{
    extern __shared__ float sm[];
    float* Qs  = sm;                    // 64 x ALD
    float* Ss  = Qs + 64 * ALD;         // 64 x ALD (scores / P)
    float* Ks0 = Ss + 64 * ALD;         // [2][KC x ALD]
    float* Vs0 = Ks0 + 2 * KC * ALD;    // [2][KC x ALD]
    float* m_s = Vs0 + 2 * KC * ALD;    // 64
    float* l_s = m_s + 64;              // 64
    float* a_s = l_s + 64;              // 64 (alpha per row)

    const int bh = blockIdx.y;
    const int b  = bh >> 4;
    const int h  = bh & 15;
    const int q0 = blockIdx.x * 64;
    const int tid = threadIdx.x;
    const int warp = tid >> 5;
    const int lane = tid & 31;
    const int g   = lane >> 2;          // group id 0..7 (acc row within 8)
    const int tg  = lane & 3;           // thread-in-group 0..3
    const int wm = warp >> 1;           // 0..3 -> 16-row stripe
    const int wn = warp & 1;            // 0..1 -> 32-col half
    const int R0 = wm * 16;
    const int C0 = wn * 32;
    const float scale = 0.125f;

    auto prefetch_kv = [&](int s, int jt) {
        float* Ks = Ks0 + s * KC * ALD;
        float* Vs = Vs0 + s * KC * ALD;
        const int j0 = jt * KC;
        #pragma unroll
        for (int i = tid; i < 1024; i += 256) {
            int row = i >> 4, c4 = i & 15;
            size_t gidx = (size_t)(b * TENC + j0 + row) * DM + h * DH + c4 * 4;
            cp_async16(&Ks[row * ALD + c4 * 4], &K[gidx]);
            cp_async16(&Vs[row * ALD + c4 * 4], &V[gidx]);
        }
        cp_commit();
    };

    // Load Q tile (64x64), pre-scaled (values tf32; x0.125 exact)
    #pragma unroll
    for (int i = tid; i < 1024; i += 256) {
        int row = i >> 4, c4 = i & 15;
        float4 v = *reinterpret_cast<const float4*>(
            &Q[(size_t)(b * TDEC + q0 + row) * DM + h * DH + c4 * 4]);
        float* dst = &Qs[row * ALD + c4 * 4];
        dst[0] = v.x * scale; dst[1] = v.y * scale;
        dst[2] = v.z * scale; dst[3] = v.w * scale;
    }
    if (tid < 64) { m_s[tid] = -1e30f; l_s[tid] = 0.0f; }

    // Register O accumulator: 4 n-tiles (n8) x 4 f32 = 16x32 warp tile
    float o[4][4];
    #pragma unroll
    for (int nt = 0; nt < 4; nt++)
        #pragma unroll
        for (int e = 0; e < 4; e++) o[nt][e] = 0.0f;

    prefetch_kv(0, 0);

    for (int jt = 0; jt < NJT; jt++) {
        cp_wait_all();
        __syncthreads();
        if (jt + 1 < NJT) prefetch_kv((jt + 1) & 1, jt + 1);
        const int st = jt & 1;
        float* Ks = Ks0 + st * KC * ALD;
        float* Vs = Vs0 + st * KC * ALD;

        // ---- S = Qs @ Ks^T : 64 x 64, warp tile 16 x 32 (wmma) ----
        {
            wmma::fragment<wmma::accumulator, 16, 16, 8, float> sacc[2];
            wmma::fill_fragment(sacc[0], 0.0f);
            wmma::fill_fragment(sacc[1], 0.0f);
            #pragma unroll
            for (int kk = 0; kk < 64; kk += 8) {
                wmma::fragment<wmma::matrix_a, 16, 16, 8, wmma::precision::tf32, wmma::row_major> afr;
                wmma::load_matrix_sync(afr, &Qs[R0 * ALD + kk], ALD);
                #pragma unroll
                for (int nt = 0; nt < 2; nt++) {
                    wmma::fragment<wmma::matrix_b, 16, 16, 8, wmma::precision::tf32, wmma::col_major> bfr;
                    wmma::load_matrix_sync(bfr, &Ks[(C0 + nt * 16) * ALD + kk], ALD);
                    wmma::mma_sync(sacc[nt], afr, bfr, sacc[nt]);
                }
            }
            #pragma unroll
            for (int nt = 0; nt < 2; nt++)
                wmma::store_matrix_sync(&Ss[R0 * ALD + C0 + nt * 16],
                                        sacc[nt], ALD, wmma::mem_row_major);
        }
        __syncthreads();

        // ---- online softmax: 4 threads/row, 16 strided cols each ----
        {
            int r = tid >> 2, seg = tid & 3;
            float* Sr = &Ss[r * ALD];
            float mx = -1e30f;
            #pragma unroll
            for (int c = 0; c < 16; c++) mx = fmaxf(mx, Sr[seg + 4 * c]);
            mx = fmaxf(mx, __shfl_xor_sync(0xffffffffu, mx, 1));
            mx = fmaxf(mx, __shfl_xor_sync(0xffffffffu, mx, 2));
            float mold = m_s[r];
            float mnew = fmaxf(mold, mx);
            float alpha = __expf(mold - mnew);
            float sum = 0.0f;
            #pragma unroll
            for (int c = 0; c < 16; c++) {
                float p = __expf(Sr[seg + 4 * c] - mnew);
                sum += p;
                Sr[seg + 4 * c] = tf32_round(p);
            }
            sum += __shfl_xor_sync(0xffffffffu, sum, 1);
            sum += __shfl_xor_sync(0xffffffffu, sum, 2);
            if (seg == 0) {
                m_s[r] = mnew;
                l_s[r] = l_s[r] * alpha + sum;
                a_s[r] = alpha;
            }
        }
        __syncthreads();

        // ---- O = O*alpha + P @ V : PTX mma, O in registers ----
        {
            const float alo = a_s[R0 + g];
            const float ahi = a_s[R0 + 8 + g];
            #pragma unroll
            for (int nt = 0; nt < 4; nt++) {
                o[nt][0] *= alo; o[nt][1] *= alo;
                o[nt][2] *= ahi; o[nt][3] *= ahi;
            }
            #pragma unroll
            for (int k0 = 0; k0 < KC; k0 += 8) {
                uint32_t a[4];
                const float* Pr = &Ss[(R0 + g) * ALD + k0 + tg];
                a[0] = __float_as_uint(Pr[0]);
                a[1] = __float_as_uint(Pr[8 * ALD]);
                a[2] = __float_as_uint(Pr[4]);
                a[3] = __float_as_uint(Pr[8 * ALD + 4]);
                #pragma unroll
                for (int nt = 0; nt < 4; nt++) {
                    uint32_t bb[2];
                    const float* Vr = &Vs[(k0 + tg) * ALD + C0 + nt * 8 + g];
                    bb[0] = __float_as_uint(Vr[0]);
                    bb[1] = __float_as_uint(Vr[4 * ALD]);
                    mma16n8k8(o[nt], a, bb);
                }
            }
        }
        // next iteration's top barrier protects Ss / stage reuse
    }
    __syncthreads();

    // Epilogue: Y rows R0+g (lo) and R0+8+g (hi), cols C0+8*nt+2*tg{,+1}
    {
        const float inv_lo = 1.0f / l_s[R0 + g];
        const float inv_hi = 1.0f / l_s[R0 + 8 + g];
        const size_t row_lo = (size_t)(b * TDEC + q0 + R0 + g) * DM + h * DH;
        const size_t row_hi = row_lo + (size_t)8 * DM;
        #pragma unroll
        for (int nt = 0; nt < 4; nt++) {
            const int c = C0 + nt * 8 + 2 * tg;
            float2 vlo, vhi;
            vlo.x = tf32_round(o[nt][0] * inv_lo);
            vlo.y = tf32_round(o[nt][1] * inv_lo);
            vhi.x = tf32_round(o[nt][2] * inv_hi);
            vhi.y = tf32_round(o[nt][3] * inv_hi);
            *reinterpret_cast<float2*>(&Y[row_lo + c]) = vlo;
            *reinterpret_cast<float2*>(&Y[row_hi + c]) = vhi;
        }
    }
}

// ---------------------------------------------------------------------------
// Launcher.  Launch index 5 = attn_kernel (ncu -s 5 -c 1 profiles it).
// ---------------------------------------------------------------------------
extern "C" void kernel_launch(void* const* d_in, const int* in_sizes, int n_in,
                              void* d_out, int out_size)
{
    const float* tgt    = (const float*)d_in[0];
    const float* memory = (const float*)d_in[1];
    const float* W_q    = (const float*)d_in[2];
    const float* b_q    = (const float*)d_in[3];
    const float* W_k    = (const float*)d_in[4];
    const float* b_k    = (const float*)d_in[5];
    const float* W_v    = (const float*)d_in[6];
    const float* b_v    = (const float*)d_in[7];
    const float* W_o    = (const float*)d_in[8];
    const float* b_o    = (const float*)d_in[9];
    float* out = (float*)d_out;

    float *gQ, *gK, *gV, *gY, *gXr, *gMr, *wq, *wk, *wv, *wo;
    cudaGetSymbolAddress((void**)&gQ, g_Q);
    cudaGetSymbolAddress((void**)&gK, g_K);
    cudaGetSymbolAddress((void**)&gV, g_V);
    cudaGetSymbolAddress((void**)&gY, g_Y);
    cudaGetSymbolAddress((void**)&gXr, g_Xr);
    cudaGetSymbolAddress((void**)&gMr, g_Mr);
    cudaGetSymbolAddress((void**)&wq, g_Wq);
    cudaGetSymbolAddress((void**)&wk, g_Wk);
    cudaGetSymbolAddress((void**)&wv, g_Wv);
    cudaGetSymbolAddress((void**)&wo, g_Wo);

    cudaFuncSetAttribute(gemm_tf32_kernel, cudaFuncAttributeMaxDynamicSharedMemorySize,
                         GEMM_SMEM_BYTES);
    cudaFuncSetAttribute(attn_kernel, cudaFuncAttributeMaxDynamicSharedMemorySize,
                         ATT_SMEM_BYTES);

    const int nact = BT * DM;    // 4M
    const int nw = DM * DM;      // 1M

    // 0,1: pre-round all GEMM operands to tf32
    round3_kernel<<<1184, 256>>>(tgt, gXr, nact, W_q, wq, nw, W_k, wk, nw);
    round3_kernel<<<1184, 256>>>(memory, gMr, nact, W_v, wv, nw, W_o, wo, nw);

    dim3 ggrid(DM / 128, BT / 128);   // (8, 32)
    // 2,3,4: projections with fused bias + tf32 round
    gemm_tf32_kernel<<<ggrid, 256, GEMM_SMEM_BYTES>>>(gXr, wq, b_q, gQ, DM, DM, 1);
    gemm_tf32_kernel<<<ggrid, 256, GEMM_SMEM_BYTES>>>(gMr, wk, b_k, gK, DM, DM, 1);
    gemm_tf32_kernel<<<ggrid, 256, GEMM_SMEM_BYTES>>>(gMr, wv, b_v, gV, DM, DM, 1);
    // 5: attention (profiled launch)
    attn_kernel<<<dim3(TDEC / 64, NB * NHEADS), 256, ATT_SMEM_BYTES>>>(gQ, gK, gV, gY);
    // 6: output projection (no rounding on final output)
    gemm_tf32_kernel<<<ggrid, 256, GEMM_SMEM_BYTES>>>(gY, wo, b_o, out, DM, DM, 0);
}